// round 1
// baseline (speedup 1.0000x reference)
#include <cuda_runtime.h>
#include <cstdint>

// Problem constants (fixed by the dataset problem)
#define B_   32
#define T_   1000
#define I_   512
#define H_   1024
#define BT_  (B_ * T_)          // 32000
#define N2_  (2 * H_)           // 2048 (Wx | Wzx stacked)

// ---------------- static device scratch (no allocations allowed) ----------------
__device__ float g_ff[(size_t)BT_ * N2_];     // 262 MB: [32000][2048] = [Wx | Wzx]
__device__ float g_psum[8 * N2_];
__device__ float g_psq[8 * N2_];
__device__ float g_bns[N2_];                  // scale  = gamma * rsqrt(var+eps)
__device__ float g_bnb[N2_];                  // bias   = beta - mean*scale
__device__ float g_yping[B_ * H_];            // y buffers, transposed [h][b]
__device__ float g_ypong[B_ * H_];
__device__ unsigned g_flags[128];             // monotonic grid-barrier flags (zero-init)

// =================================================================================
// 1) Feedforward GEMM: C[m][n] = sum_k A[m][k] * Brow[n][k]
//    A = x [32000 x 512], Brow = W (n<1024) or Wz (n>=1024), both [1024 x 512]
//    Classic 128x128x8 SGEMM, 256 threads, 8x8 per-thread tile. No bounds checks
//    needed (32000%128==0, 2048%128==0, 512%8==0).
// =================================================================================
__global__ __launch_bounds__(256) void ff_gemm(const float* __restrict__ x,
                                               const float* __restrict__ W,
                                               const float* __restrict__ Wz)
{
    __shared__ float As[8][128];
    __shared__ float Bs[8][128];

    const int bn = blockIdx.x;   // 0..15  (n tile)
    const int bm = blockIdx.y;   // 0..249 (m tile)
    const int tid = threadIdx.x;

    const float* A = x + (size_t)bm * 128 * I_;
    const float* Bmat = (bn < 8) ? (W + (size_t)bn * 128 * I_)
                                 : (Wz + (size_t)(bn - 8) * 128 * I_);

    const int lr = tid >> 1;          // 0..127 row within tile
    const int lc = (tid & 1) * 4;     // 0 or 4

    const int tx = tid & 15;          // n micro
    const int ty = tid >> 4;          // m micro

    float acc[8][8];
#pragma unroll
    for (int i = 0; i < 8; i++)
#pragma unroll
        for (int j = 0; j < 8; j++) acc[i][j] = 0.f;

    for (int k0 = 0; k0 < I_; k0 += 8) {
        float4 a4 = *(const float4*)(A + (size_t)lr * I_ + k0 + lc);
        float4 b4 = *(const float4*)(Bmat + (size_t)lr * I_ + k0 + lc);
        As[lc + 0][lr] = a4.x; As[lc + 1][lr] = a4.y;
        As[lc + 2][lr] = a4.z; As[lc + 3][lr] = a4.w;
        Bs[lc + 0][lr] = b4.x; Bs[lc + 1][lr] = b4.y;
        Bs[lc + 2][lr] = b4.z; Bs[lc + 3][lr] = b4.w;
        __syncthreads();
#pragma unroll
        for (int k = 0; k < 8; k++) {
            float ar[8], br[8];
            *(float4*)&ar[0] = *(const float4*)&As[k][ty * 8];
            *(float4*)&ar[4] = *(const float4*)&As[k][ty * 8 + 4];
            *(float4*)&br[0] = *(const float4*)&Bs[k][tx * 8];
            *(float4*)&br[4] = *(const float4*)&Bs[k][tx * 8 + 4];
#pragma unroll
            for (int i = 0; i < 8; i++)
#pragma unroll
                for (int j = 0; j < 8; j++)
                    acc[i][j] = fmaf(ar[i], br[j], acc[i][j]);
        }
        __syncthreads();
    }

    const int row0 = bm * 128 + ty * 8;
    const int col0 = bn * 128 + tx * 8;
#pragma unroll
    for (int i = 0; i < 8; i++) {
        float* dst = g_ff + (size_t)(row0 + i) * N2_ + col0;
        *(float4*)dst = make_float4(acc[i][0], acc[i][1], acc[i][2], acc[i][3]);
        *(float4*)(dst + 4) = make_float4(acc[i][4], acc[i][5], acc[i][6], acc[i][7]);
    }
}

// =================================================================================
// 2) BatchNorm stats, two-stage deterministic reduction
// =================================================================================
__global__ __launch_bounds__(256) void bn_partial()
{
    const int cb = blockIdx.x;    // 0..63 (column group of 32)
    const int rb = blockIdx.y;    // 0..7  (row chunk of 4000)
    const int c = threadIdx.x & 31;
    const int r = threadIdx.x >> 5;       // 0..7
    const int col = cb * 32 + c;

    float s = 0.f, q = 0.f;
    const int rend = (rb + 1) * 4000;
    for (int row = rb * 4000 + r; row < rend; row += 8) {
        float v = __ldcg(&g_ff[(size_t)row * N2_ + col]);
        s += v; q += v * v;
    }
    __shared__ float ss[8][32], sq[8][32];
    ss[r][c] = s; sq[r][c] = q;
    __syncthreads();
    if (r == 0) {
#pragma unroll
        for (int i = 1; i < 8; i++) { s += ss[i][c]; q += sq[i][c]; }
        g_psum[rb * N2_ + col] = s;
        g_psq[rb * N2_ + col] = q;
    }
}

__global__ void bn_final(const float* __restrict__ gamma, const float* __restrict__ beta,
                         const float* __restrict__ gamma_z, const float* __restrict__ beta_z)
{
    const int n = blockIdx.x * 1024 + threadIdx.x;   // 0..2047
    float s = 0.f, q = 0.f;
#pragma unroll
    for (int i = 0; i < 8; i++) { s += g_psum[i * N2_ + n]; q += g_psq[i * N2_ + n]; }
    const float invN = 1.f / (float)BT_;
    float mean = s * invN;
    float var = q * invN - mean * mean;
    float ga = (n < H_) ? gamma[n] : gamma_z[n - H_];
    float be = (n < H_) ? beta[n] : beta_z[n - H_];
    float sc = ga * rsqrtf(var + 1e-5f);
    g_bns[n] = sc;
    g_bnb[n] = be - mean * sc;
}

// =================================================================================
// 3) Persistent LiGRU recurrence
//    128 blocks x 128 threads (1 block/SM, all co-resident).
//    Block owns h columns [blk*8, blk*8+8). Warp w owns (hA = h0+2w, hB = hA+1),
//    both gates -> 4 dot products per lane (lane = batch).
//    smem: y_s[1024][32] (y_{t-1} transposed, 128 KB) + wpack[1024][16] (64 KB).
//    Grid barrier: monotonic per-block flag array (replay-safe, no reset needed).
// =================================================================================
#define RBLK 128
#define SMEM_BYTES ((32768 + 16384) * sizeof(float))   // 192 KB

__global__ __launch_bounds__(128, 1) void ligru_recur(const float* __restrict__ V,
                                                      const float* __restrict__ Vz,
                                                      float* __restrict__ out)
{
    extern __shared__ float sm[];
    float* y_s = sm;              // [k*32 + b], k = 0..1023 (h-index of y), b = 0..31
    float* wpack = sm + 32768;    // [k*16 + w*4 + {VhA, VzhA, VhB, VzhB}]

    const int tid = threadIdx.x;
    const int blk = blockIdx.x;
    const int w = tid >> 5;
    const int lane = tid & 31;
    const int h0 = blk * 8;
    const int hA = h0 + 2 * w;
    const int hB = hA + 1;

    // Build packed weight tile in smem (once per launch)
    for (int idx = tid; idx < 16384; idx += 128) {
        int k = idx >> 4;
        int j = idx & 15;
        int ww = j >> 2, jj = j & 3;
        int h = h0 + 2 * ww + (jj >> 1);
        const float* M = (jj & 1) ? Vz : V;
        wpack[idx] = M[(size_t)h * H_ + k];
    }
    // Zero this block's slice of the ping buffer (y_0 = 0)
    for (int i = tid; i < 256; i += 128) g_yping[blk * 256 + i] = 0.f;

    // BN affine coefficients for our 4 (col, gate) sets
    const float s_cA = g_bns[hA],       b_cA = g_bnb[hA];
    const float s_zA = g_bns[H_ + hA],  b_zA = g_bnb[H_ + hA];
    const float s_cB = g_bns[hB],       b_cB = g_bnb[hB];
    const float s_zB = g_bns[H_ + hB],  b_zB = g_bnb[H_ + hB];

    // Barrier base: all flags are equal at launch start; read our own flag.
    __shared__ unsigned sbase;
    if (tid == 0) sbase = *((volatile unsigned*)&g_flags[blk]);
    __syncthreads();
    const unsigned base = sbase;
    const volatile unsigned* vf = g_flags;

    // ---- init barrier (ping zeroed everywhere before first read) ----
    __threadfence();
    __syncthreads();
    if (tid == 0) *((volatile unsigned*)&g_flags[blk]) = base + 1;
    while (vf[tid] < base + 1) __nanosleep(32);
    __syncthreads();

    for (int t = 0; t < T_; t++) {
        const float* ybuf = (t & 1) ? g_ypong : g_yping;
        float* ynext      = (t & 1) ? g_yping : g_ypong;

        // Stage y_{t-1} into smem (L2 loads; every block reads the full 128 KB)
        for (int i = tid * 4; i < B_ * H_; i += 512) {
            float4 v = __ldcg((const float4*)(ybuf + i));
            *(float4*)(y_s + i) = v;
        }
        // Prefetch normalized-input operands for this (b=lane, t)
        const size_t rowFF = ((size_t)lane * T_ + t) * N2_;
        float2 wx2 = __ldcg((const float2*)(g_ff + rowFF + hA));
        float2 wz2 = __ldcg((const float2*)(g_ff + rowFF + H_ + hA));
        __syncthreads();

        // 4 dot products of length 1024 (lane = batch)
        float a0 = 0.f, a1 = 0.f, a2 = 0.f, a3 = 0.f;
        const float4* wp4 = (const float4*)wpack + w;   // element k -> wp4[4*k]
#pragma unroll 8
        for (int k = 0; k < H_; k++) {
            float y = y_s[k * 32 + lane];
            float4 wv = wp4[k * 4];
            a0 = fmaf(wv.x, y, a0);
            a1 = fmaf(wv.y, y, a1);
            a2 = fmaf(wv.z, y, a2);
            a3 = fmaf(wv.w, y, a3);
        }

        const float ypA = y_s[hA * 32 + lane];
        const float ypB = y_s[hB * 32 + lane];

        float cA = fmaxf(fmaf(wx2.x, s_cA, b_cA) + a0, 0.f);
        float zA = 1.f / (1.f + __expf(-(fmaf(wz2.x, s_zA, b_zA) + a1)));
        float cB = fmaxf(fmaf(wx2.y, s_cB, b_cB) + a2, 0.f);
        float zB = 1.f / (1.f + __expf(-(fmaf(wz2.y, s_zB, b_zB) + a3)));

        float yA = zA * ypA + (1.f - zA) * cA;
        float yB = zB * ypB + (1.f - zB) * cB;

        ynext[hA * 32 + lane] = yA;
        ynext[hB * 32 + lane] = yB;
        *(float2*)(out + (size_t)lane * (T_ * H_) + (size_t)t * H_ + hA) = make_float2(yA, yB);

        // ---- grid barrier for step t ----
        __threadfence();
        __syncthreads();
        const unsigned target = base + 2 + (unsigned)t;
        if (tid == 0) *((volatile unsigned*)&g_flags[blk]) = target;
        while (vf[tid] < target) __nanosleep(32);
        __syncthreads();
    }
}

// =================================================================================
// launch
// =================================================================================
extern "C" void kernel_launch(void* const* d_in, const int* in_sizes, int n_in,
                              void* d_out, int out_size)
{
    const float* x       = (const float*)d_in[0];
    const float* W       = (const float*)d_in[1];
    const float* Wz      = (const float*)d_in[2];
    const float* V       = (const float*)d_in[3];
    const float* Vz      = (const float*)d_in[4];
    const float* gamma   = (const float*)d_in[5];
    const float* beta    = (const float*)d_in[6];
    const float* gamma_z = (const float*)d_in[7];
    const float* beta_z  = (const float*)d_in[8];
    float* out = (float*)d_out;

    (void)in_sizes; (void)n_in; (void)out_size;

    // Opt-in to 192 KB dynamic smem for the persistent recurrence kernel.
    cudaFuncSetAttribute(ligru_recur, cudaFuncAttributeMaxDynamicSharedMemorySize,
                         (int)SMEM_BYTES);

    ff_gemm<<<dim3(16, 250), 256>>>(x, W, Wz);
    bn_partial<<<dim3(64, 8), 256>>>();
    bn_final<<<2, 1024>>>(gamma, beta, gamma_z, beta_z);
    ligru_recur<<<RBLK, 128, SMEM_BYTES>>>(V, Vz, out);
}

// round 2
// speedup vs baseline: 1.3754x; 1.3754x over previous
#include <cuda_runtime.h>
#include <cstdint>

// Problem constants (fixed by the dataset problem)
#define B_   32
#define T_   1000
#define I_   512
#define H_   1024
#define BT_  (B_ * T_)          // 32000
#define N2_  (2 * H_)           // 2048 (Wx | Wzx stacked)

// ---------------- static device scratch (no allocations allowed) ----------------
__device__ float g_ff[(size_t)BT_ * N2_];     // 262 MB: [32000][2048] = [Wx | Wzx]
__device__ float g_psum[8 * N2_];
__device__ float g_psq[8 * N2_];
__device__ float g_bns[N2_];                  // scale  = gamma * rsqrt(var+eps)
__device__ float g_bnb[N2_];                  // bias   = beta - mean*scale
__device__ float g_yping[B_ * H_];            // y buffers, transposed [h][b]
__device__ float g_ypong[B_ * H_];
__device__ unsigned g_flags[128];             // monotonic grid-barrier flags (zero-init)

// =================================================================================
// 1) Feedforward GEMM: C[m][n] = sum_k A[m][k] * Brow[n][k]
//    A = x [32000 x 512], Brow = W (n<1024) or Wz (n>=1024), both [1024 x 512]
//    Classic 128x128x8 SGEMM, 256 threads, 8x8 per-thread tile.
// =================================================================================
__global__ __launch_bounds__(256) void ff_gemm(const float* __restrict__ x,
                                               const float* __restrict__ W,
                                               const float* __restrict__ Wz)
{
    __shared__ float As[8][128];
    __shared__ float Bs[8][128];

    const int bn = blockIdx.x;   // 0..15  (n tile)
    const int bm = blockIdx.y;   // 0..249 (m tile)
    const int tid = threadIdx.x;

    const float* A = x + (size_t)bm * 128 * I_;
    const float* Bmat = (bn < 8) ? (W + (size_t)bn * 128 * I_)
                                 : (Wz + (size_t)(bn - 8) * 128 * I_);

    const int lr = tid >> 1;          // 0..127 row within tile
    const int lc = (tid & 1) * 4;     // 0 or 4

    const int tx = tid & 15;          // n micro
    const int ty = tid >> 4;          // m micro

    float acc[8][8];
#pragma unroll
    for (int i = 0; i < 8; i++)
#pragma unroll
        for (int j = 0; j < 8; j++) acc[i][j] = 0.f;

    for (int k0 = 0; k0 < I_; k0 += 8) {
        float4 a4 = *(const float4*)(A + (size_t)lr * I_ + k0 + lc);
        float4 b4 = *(const float4*)(Bmat + (size_t)lr * I_ + k0 + lc);
        As[lc + 0][lr] = a4.x; As[lc + 1][lr] = a4.y;
        As[lc + 2][lr] = a4.z; As[lc + 3][lr] = a4.w;
        Bs[lc + 0][lr] = b4.x; Bs[lc + 1][lr] = b4.y;
        Bs[lc + 2][lr] = b4.z; Bs[lc + 3][lr] = b4.w;
        __syncthreads();
#pragma unroll
        for (int k = 0; k < 8; k++) {
            float ar[8], br[8];
            *(float4*)&ar[0] = *(const float4*)&As[k][ty * 8];
            *(float4*)&ar[4] = *(const float4*)&As[k][ty * 8 + 4];
            *(float4*)&br[0] = *(const float4*)&Bs[k][tx * 8];
            *(float4*)&br[4] = *(const float4*)&Bs[k][tx * 8 + 4];
#pragma unroll
            for (int i = 0; i < 8; i++)
#pragma unroll
                for (int j = 0; j < 8; j++)
                    acc[i][j] = fmaf(ar[i], br[j], acc[i][j]);
        }
        __syncthreads();
    }

    const int row0 = bm * 128 + ty * 8;
    const int col0 = bn * 128 + tx * 8;
#pragma unroll
    for (int i = 0; i < 8; i++) {
        float* dst = g_ff + (size_t)(row0 + i) * N2_ + col0;
        *(float4*)dst = make_float4(acc[i][0], acc[i][1], acc[i][2], acc[i][3]);
        *(float4*)(dst + 4) = make_float4(acc[i][4], acc[i][5], acc[i][6], acc[i][7]);
    }
}

// =================================================================================
// 2) BatchNorm stats, two-stage deterministic reduction
// =================================================================================
__global__ __launch_bounds__(256) void bn_partial()
{
    const int cb = blockIdx.x;    // 0..63 (column group of 32)
    const int rb = blockIdx.y;    // 0..7  (row chunk of 4000)
    const int c = threadIdx.x & 31;
    const int r = threadIdx.x >> 5;       // 0..7
    const int col = cb * 32 + c;

    float s = 0.f, q = 0.f;
    const int rend = (rb + 1) * 4000;
    for (int row = rb * 4000 + r; row < rend; row += 8) {
        float v = __ldcg(&g_ff[(size_t)row * N2_ + col]);
        s += v; q += v * v;
    }
    __shared__ float ss[8][32], sq[8][32];
    ss[r][c] = s; sq[r][c] = q;
    __syncthreads();
    if (r == 0) {
#pragma unroll
        for (int i = 1; i < 8; i++) { s += ss[i][c]; q += sq[i][c]; }
        g_psum[rb * N2_ + col] = s;
        g_psq[rb * N2_ + col] = q;
    }
}

__global__ void bn_final(const float* __restrict__ gamma, const float* __restrict__ beta,
                         const float* __restrict__ gamma_z, const float* __restrict__ beta_z)
{
    const int n = blockIdx.x * 1024 + threadIdx.x;   // 0..2047
    float s = 0.f, q = 0.f;
#pragma unroll
    for (int i = 0; i < 8; i++) { s += g_psum[i * N2_ + n]; q += g_psq[i * N2_ + n]; }
    const float invN = 1.f / (float)BT_;
    float mean = s * invN;
    float var = q * invN - mean * mean;
    float ga = (n < H_) ? gamma[n] : gamma_z[n - H_];
    float be = (n < H_) ? beta[n] : beta_z[n - H_];
    float sc = ga * rsqrtf(var + 1e-5f);
    g_bns[n] = sc;
    g_bnb[n] = be - mean * sc;
}

// =================================================================================
// 3) Persistent LiGRU recurrence — v2
//    128 blocks x 512 threads (16 warps; 4 per SMSP for latency hiding).
//    Block owns 8 h-columns [blk*8, blk*8+8).
//    Warp w: kseg = w>>1 (k chunk of 128), c = w&1 (column group of 4).
//    Each warp: 8 accumulators = 4 columns x 2 gates over its 128 k's.
//    k-partials reduced via smem; warps 0/1 finalize (activations + stores).
//    smem: y_s[1024][32] (128 KB) + wpack (64 KB) + part (16 KB) = 208 KB.
// =================================================================================
#define RBLK 128
#define RTHREADS 512
#define Y_S_FLOATS   (B_ * H_)          // 32768
#define WPACK_FLOATS (H_ * 16)          // 16384
#define PART_FLOATS  (16 * 8 * 32)      // 4096
#define SMEM_BYTES ((Y_S_FLOATS + WPACK_FLOATS + PART_FLOATS) * sizeof(float))

__global__ __launch_bounds__(RTHREADS, 1) void ligru_recur(const float* __restrict__ V,
                                                           const float* __restrict__ Vz,
                                                           float* __restrict__ out)
{
    extern __shared__ float sm[];
    float* y_s   = sm;                           // [k*32 + b]
    float* wpack = sm + Y_S_FLOATS;              // scalar idx = k*16 + c*8 + g*4 + j
    float* part  = sm + Y_S_FLOATS + WPACK_FLOATS; // [(w*8 + i)*32 + lane]

    const int tid  = threadIdx.x;
    const int blk  = blockIdx.x;
    const int w    = tid >> 5;        // 0..15
    const int lane = tid & 31;
    const int kseg = w >> 1;          // 0..7
    const int c    = w & 1;           // 0..1
    const int h0   = blk * 8;
    const int hc   = h0 + 4 * c;      // first of this warp's 4 columns

    // Build packed weight tile in smem (once per launch)
    for (int idx = tid; idx < WPACK_FLOATS; idx += RTHREADS) {
        int k  = idx >> 4;
        int cc = (idx >> 3) & 1;
        int g  = (idx >> 2) & 1;
        int j  = idx & 3;
        int h  = h0 + 4 * cc + j;
        const float* M = g ? Vz : V;
        wpack[idx] = M[(size_t)h * H_ + k];
    }
    // Zero this block's slice of the ping buffer (y_0 = 0)
    if (tid < 256) g_yping[blk * 256 + tid] = 0.f;

    // BN affine coefficients for this warp's 4 columns (used by final warps 0/1)
    float s_c[4], b_c[4], s_z[4], b_z[4];
    if (w < 2) {
#pragma unroll
        for (int j = 0; j < 4; j++) {
            s_c[j] = g_bns[hc + j];        b_c[j] = g_bnb[hc + j];
            s_z[j] = g_bns[H_ + hc + j];   b_z[j] = g_bnb[H_ + hc + j];
        }
    }

    // Barrier base (flags are monotonic across graph replays)
    __shared__ unsigned sbase;
    if (tid == 0) sbase = *((volatile unsigned*)&g_flags[blk]);
    __syncthreads();
    const unsigned base = sbase;
    const volatile unsigned* vf = g_flags;

    // ---- init barrier (ping zeroed everywhere before first read) ----
    __threadfence();
    __syncthreads();
    if (tid == 0) *((volatile unsigned*)&g_flags[blk]) = base + 1;
    if (tid < 128) { while (vf[tid] < base + 1) __nanosleep(32); }
    __syncthreads();

    const float4* wp = (const float4*)wpack + c * 2;   // per k: wp[4k] = V, wp[4k+1] = Vz

    for (int t = 0; t < T_; t++) {
        const float* ybuf = (t & 1) ? g_ypong : g_yping;
        float* ynext      = (t & 1) ? g_yping : g_ypong;

        // Early loads for finalizer warps (independent of y staging)
        float4 wx4, wz4, yp4;
        if (w < 2) {
            const size_t rowFF = ((size_t)lane * T_ + t) * N2_;
            wx4 = __ldcg((const float4*)(g_ff + rowFF + hc));
            wz4 = __ldcg((const float4*)(g_ff + rowFF + H_ + hc));
            yp4.x = __ldcg(ybuf + (hc + 0) * 32 + lane);
            yp4.y = __ldcg(ybuf + (hc + 1) * 32 + lane);
            yp4.z = __ldcg(ybuf + (hc + 2) * 32 + lane);
            yp4.w = __ldcg(ybuf + (hc + 3) * 32 + lane);
        }

        // Stage y_{t-1} into smem (all 512 threads, float4)
        for (int i = tid; i < Y_S_FLOATS / 4; i += RTHREADS) {
            float4 v = __ldcg((const float4*)ybuf + i);
            *((float4*)y_s + i) = v;
        }
        __syncthreads();

        // Partial dot products over this warp's 128-k segment, 4 cols x 2 gates
        float a0 = 0.f, a1 = 0.f, a2 = 0.f, a3 = 0.f;
        float a4 = 0.f, a5 = 0.f, a6 = 0.f, a7 = 0.f;
        {
            const int kbeg = kseg * 128;
#pragma unroll 4
            for (int k = kbeg; k < kbeg + 128; k++) {
                float y  = y_s[k * 32 + lane];
                float4 v = wp[k * 4];
                float4 z = wp[k * 4 + 1];
                a0 = fmaf(v.x, y, a0);
                a1 = fmaf(v.y, y, a1);
                a2 = fmaf(v.z, y, a2);
                a3 = fmaf(v.w, y, a3);
                a4 = fmaf(z.x, y, a4);
                a5 = fmaf(z.y, y, a5);
                a6 = fmaf(z.z, y, a6);
                a7 = fmaf(z.w, y, a7);
            }
        }
        float* pw = part + (w * 8) * 32 + lane;
        pw[0 * 32] = a0; pw[1 * 32] = a1; pw[2 * 32] = a2; pw[3 * 32] = a3;
        pw[4 * 32] = a4; pw[5 * 32] = a5; pw[6 * 32] = a6; pw[7 * 32] = a7;
        __syncthreads();

        // Finalize: warps 0 (c=0) and 1 (c=1) reduce ksegs + activations + stores
        if (w < 2) {
            float s[8];
#pragma unroll
            for (int i = 0; i < 8; i++) {
                float acc = 0.f;
#pragma unroll
                for (int ks = 0; ks < 8; ks++)
                    acc += part[((ks * 2 + c) * 8 + i) * 32 + lane];
                s[i] = acc;
            }
            float yv[4];
            const float ypj[4] = { yp4.x, yp4.y, yp4.z, yp4.w };
            const float wxj[4] = { wx4.x, wx4.y, wx4.z, wx4.w };
            const float wzj[4] = { wz4.x, wz4.y, wz4.z, wz4.w };
#pragma unroll
            for (int j = 0; j < 4; j++) {
                float ct = fmaxf(fmaf(wxj[j], s_c[j], b_c[j]) + s[j], 0.f);
                float zt = 1.f / (1.f + __expf(-(fmaf(wzj[j], s_z[j], b_z[j]) + s[4 + j])));
                yv[j] = zt * ypj[j] + (1.f - zt) * ct;
                ynext[(hc + j) * 32 + lane] = yv[j];
            }
            *(float4*)(out + (size_t)lane * (T_ * H_) + (size_t)t * H_ + hc) =
                make_float4(yv[0], yv[1], yv[2], yv[3]);
            __threadfence();
        }

        // ---- grid barrier for step t (skip after last step) ----
        if (t < T_ - 1) {
            __syncthreads();
            const unsigned target = base + 2 + (unsigned)t;
            if (tid == 0) *((volatile unsigned*)&g_flags[blk]) = target;
            if (tid < 128) { while (vf[tid] < target) __nanosleep(32); }
            __syncthreads();
        }
    }
}

// =================================================================================
// launch
// =================================================================================
extern "C" void kernel_launch(void* const* d_in, const int* in_sizes, int n_in,
                              void* d_out, int out_size)
{
    const float* x       = (const float*)d_in[0];
    const float* W       = (const float*)d_in[1];
    const float* Wz      = (const float*)d_in[2];
    const float* V       = (const float*)d_in[3];
    const float* Vz      = (const float*)d_in[4];
    const float* gamma   = (const float*)d_in[5];
    const float* beta    = (const float*)d_in[6];
    const float* gamma_z = (const float*)d_in[7];
    const float* beta_z  = (const float*)d_in[8];
    float* out = (float*)d_out;

    (void)in_sizes; (void)n_in; (void)out_size;

    cudaFuncSetAttribute(ligru_recur, cudaFuncAttributeMaxDynamicSharedMemorySize,
                         (int)SMEM_BYTES);

    ff_gemm<<<dim3(16, 250), 256>>>(x, W, Wz);
    bn_partial<<<dim3(64, 8), 256>>>();
    bn_final<<<2, 1024>>>(gamma, beta, gamma_z, beta_z);
    ligru_recur<<<RBLK, RTHREADS, SMEM_BYTES>>>(V, Vz, out);
}